// round 3
// baseline (speedup 1.0000x reference)
#include <cuda_runtime.h>

#define BB  2
#define SSQ 2048
#define DDIM 1024
#define HH  16
#define DKK 64

// ---------------- scratch (static device, no allocations) ----------------
__device__ float g_Q [BB*SSQ*DDIM];
__device__ float g_K [BB*SSQ*DDIM];
__device__ float g_V [BB*SSQ*DDIM];
__device__ float g_AO[BB*SSQ*DDIM];

// ---------------- projection GEMM: C[M,N] = A[M,K]@W[K,N] + bias ---------
__global__ __launch_bounds__(256, 2)
void sgemm_bias(const float* __restrict__ A, const float* __restrict__ W,
                const float* __restrict__ bias, float* __restrict__ C,
                int M, int N, int K)
{
    __shared__ __align__(16) float As[16][128];
    __shared__ __align__(16) float Bs[16][128];
    const int tid = threadIdx.x;
    const int tx = tid & 15, ty = tid >> 4;
    const int bm = blockIdx.y * 128, bn = blockIdx.x * 128;

    float acc[8][8];
    #pragma unroll
    for (int i = 0; i < 8; i++)
        #pragma unroll
        for (int j = 0; j < 8; j++) acc[i][j] = 0.f;

    const int arow = tid >> 2, acol = (tid & 3) << 2;
    const int brow = tid >> 5, bcol = (tid & 31) << 2;

    for (int k0 = 0; k0 < K; k0 += 16) {
        #pragma unroll
        for (int h2 = 0; h2 < 2; h2++) {
            int r = arow + h2 * 64;
            float4 a = *(const float4*)&A[(size_t)(bm + r) * K + k0 + acol];
            As[acol+0][r] = a.x; As[acol+1][r] = a.y;
            As[acol+2][r] = a.z; As[acol+3][r] = a.w;
        }
        #pragma unroll
        for (int h2 = 0; h2 < 2; h2++) {
            int r = brow + h2 * 8;
            *(float4*)&Bs[r][bcol] = *(const float4*)&W[(size_t)(k0 + r) * N + bn + bcol];
        }
        __syncthreads();
        #pragma unroll
        for (int k = 0; k < 16; k++) {
            float am[8], bv2[8];
            *(float4*)&am[0]  = *(float4*)&As[k][ty << 2];
            *(float4*)&am[4]  = *(float4*)&As[k][(ty << 2) + 64];
            *(float4*)&bv2[0] = *(float4*)&Bs[k][tx << 2];
            *(float4*)&bv2[4] = *(float4*)&Bs[k][(tx << 2) + 64];
            #pragma unroll
            for (int i = 0; i < 8; i++)
                #pragma unroll
                for (int j = 0; j < 8; j++)
                    acc[i][j] += am[i] * bv2[j];
        }
        __syncthreads();
    }
    #pragma unroll
    for (int i = 0; i < 8; i++) {
        int row = bm + (ty << 2) + (i < 4 ? i : 60 + i);
        #pragma unroll
        for (int jw = 0; jw < 2; jw++) {
            int col = bn + (tx << 2) + jw * 64;
            float4 bb = *(const float4*)&bias[col];
            float4 o;
            o.x = acc[i][jw*4+0] + bb.x;
            o.y = acc[i][jw*4+1] + bb.y;
            o.z = acc[i][jw*4+2] + bb.z;
            o.w = acc[i][jw*4+3] + bb.w;
            *(float4*)&C[(size_t)row * N + col] = o;
        }
    }
}

// ---------------- flash attention with relative-position bias ------------
// tile: 64 queries x 64 keys; score GEMM is 64x192 against [K | PE-window]
// shared layout (floats):
//   sQT  [64][64]   d-major Q                      @ 0
//   sKP  [64][192]  d-major K(0..63)+PE(64..190), XOR-swizzled groups @ 4096
//   sV   [64][64]   XOR-swizzled                   @ 16384
//   sAll [64][192]  raw scores                     @ 20480
//   sP   [64][65]   probabilities                  @ 32768
//   sM/sL/sCr [64] each                            @ 36928/36992/37056
#define AT_SMEM_FLOATS 37120
#define AT_SMEM_BYTES  (AT_SMEM_FLOATS * 4)

__global__ __launch_bounds__(256, 1)
void attn_kernel(const float* __restrict__ Qg, const float* __restrict__ Kg,
                 const float* __restrict__ Vg, const float* __restrict__ pe,
                 float* __restrict__ AO)
{
    extern __shared__ float sm[];
    float* sQT  = sm;
    float* sKP  = sm + 4096;
    float* sV   = sm + 16384;
    float* sAll = sm + 20480;
    float* sP   = sm + 32768;
    float* sM   = sm + 36928;
    float* sL   = sm + 36992;
    float* sCr  = sm + 37056;

    const int tid = threadIdx.x;
    const int tx = tid & 15, ty = tid >> 4;
    const int i0 = (gridDim.x - 1 - blockIdx.x) << 6;   // heavy tiles first
    const int bh = blockIdx.y;
    const int b = bh >> 4, h = bh & 15;
    const float scale = 0.125f;

    const float* Qb = Qg + (size_t)b * SSQ * DDIM + h * DKK;
    const float* Kb = Kg + (size_t)b * SSQ * DDIM + h * DKK;
    const float* Vb = Vg + (size_t)b * SSQ * DDIM + h * DKK;

    // load Q tile, d-major
    #pragma unroll
    for (int it = 0; it < 4; it++) {
        int e = (tid << 2) + (it << 10);
        int r = e >> 6, d4 = e & 63;
        float4 q = *(const float4*)&Qb[(size_t)(i0 + r) * DDIM + d4];
        sQT[(d4+0)*64 + r] = q.x;
        sQT[(d4+1)*64 + r] = q.y;
        sQT[(d4+2)*64 + r] = q.z;
        sQT[(d4+3)*64 + r] = q.w;
    }
    if (tid < 64) { sM[tid] = -1e30f; sL[tid] = 0.f; }

    float oacc[4][4];
    #pragma unroll
    for (int i = 0; i < 4; i++)
        #pragma unroll
        for (int j = 0; j < 4; j++) oacc[i][j] = 0.f;

    __syncthreads();

    const int ntiles = (i0 >> 6) + 1;
    for (int kt = 0; kt < ntiles; kt++) {
        const int j0 = kt << 6;
        const int base0 = SSQ - 64 - i0 + j0;   // pe row = base0 + (c - r + 63)

        // K tile -> sKP cols 0..63, transposed, XOR-swizzled within 16 groups
        #pragma unroll
        for (int it = 0; it < 4; it++) {
            int e = (tid << 2) + (it << 10);
            int c = e >> 6, d4 = e & 63;
            float4 kv = *(const float4*)&Kb[(size_t)(j0 + c) * DDIM + d4];
            int g = c >> 2, cc = c & 3;
            #pragma unroll
            for (int q = 0; q < 4; q++) {
                int d = d4 + q;
                int pg = g ^ ((d >> 2) & 15);
                sKP[d*192 + (pg << 2) + cc] = ((const float*)&kv)[q];
            }
        }
        // PE window -> sKP cols 64..190 (127 rows of key_pe, clamped)
        #pragma unroll
        for (int it = 0; it < 8; it++) {
            int idx = tid + (it << 8);
            if (idx < 2032) {
                int off = idx >> 4;
                int d4 = (idx & 15) << 2;
                int l = base0 + off;
                l = l < 0 ? 0 : (l > SSQ - 1 ? SSQ - 1 : l);
                float4 pv = *(const float4*)&pe[l * DKK + d4];
                int g = (64 + off) >> 2, cc = off & 3;
                #pragma unroll
                for (int q = 0; q < 4; q++) {
                    int d = d4 + q;
                    int pg = (g & 48) | ((g & 15) ^ ((d >> 2) & 15));
                    sKP[d*192 + (pg << 2) + cc] = ((const float*)&pv)[q];
                }
            }
        }
        // V tile -> sV, XOR-swizzled
        #pragma unroll
        for (int it = 0; it < 4; it++) {
            int e = (tid << 2) + (it << 10);
            int j = e >> 6, c4 = e & 63;
            float4 vv = *(const float4*)&Vb[(size_t)(j0 + j) * DDIM + c4];
            int pg = (c4 >> 2) ^ ((j >> 2) & 15);
            *(float4*)&sV[j*64 + (pg << 2)] = vv;
        }
        __syncthreads();

        // ---- score GEMM: sc[i][0..3]=cont, [4..11]=pos window ----
        float sc[4][12];
        #pragma unroll
        for (int i = 0; i < 4; i++)
            #pragma unroll
            for (int j = 0; j < 12; j++) sc[i][j] = 0.f;

        #pragma unroll 4
        for (int d = 0; d < 64; d++) {
            int kd = (d >> 2) & 15;
            float4 qv = *(const float4*)&sQT[d*64 + (ty << 2)];
            int xg = tx ^ kd;
            float4 k0 = *(const float4*)&sKP[d*192 + (xg << 2)];
            float4 k1 = *(const float4*)&sKP[d*192 + ((16 | xg) << 2)];
            float4 k2 = *(const float4*)&sKP[d*192 + ((32 | xg) << 2)];
            const float* qf  = (const float*)&qv;
            const float* f0  = (const float*)&k0;
            const float* f1  = (const float*)&k1;
            const float* f2  = (const float*)&k2;
            #pragma unroll
            for (int i = 0; i < 4; i++) {
                float q_ = qf[i];
                #pragma unroll
                for (int j = 0; j < 4; j++) {
                    sc[i][j]     += q_ * f0[j];
                    sc[i][4 + j] += q_ * f1[j];
                    sc[i][8 + j] += q_ * f2[j];
                }
            }
        }
        #pragma unroll
        for (int i = 0; i < 4; i++) {
            int r = (ty << 2) + i;
            #pragma unroll
            for (int w = 0; w < 3; w++)
                #pragma unroll
                for (int j = 0; j < 4; j++)
                    sAll[r*192 + (w << 6) + (tx << 2) + j] = sc[i][(w << 2) + j];
        }
        __syncthreads();

        // ---- combine + online softmax (4 lanes per row) ----
        {
            int r = tid >> 2, gq = tid & 3;
            int gi = i0 + r;
            float m_old = sM[r];
            float vmax = -1e30f;
            float vals[16];
            #pragma unroll
            for (int kk = 0; kk < 16; kk++) {
                int c = gq + (kk << 2);
                float s;
                if (j0 + c <= gi) {
                    int off = c - r + 63;
                    s = (sAll[r*192 + c] + sAll[r*192 + 64 + off]) * scale;
                } else s = -1e30f;
                vals[kk] = s;
                vmax = fmaxf(vmax, s);
            }
            vmax = fmaxf(vmax, __shfl_xor_sync(0xffffffffu, vmax, 1));
            vmax = fmaxf(vmax, __shfl_xor_sync(0xffffffffu, vmax, 2));
            float m_new = fmaxf(m_old, vmax);
            float corr = __expf(m_old - m_new);
            float lsum = 0.f;
            #pragma unroll
            for (int kk = 0; kk < 16; kk++) {
                float p = __expf(vals[kk] - m_new);
                lsum += p;
                sP[r*65 + gq + (kk << 2)] = p;
            }
            lsum += __shfl_xor_sync(0xffffffffu, lsum, 1);
            lsum += __shfl_xor_sync(0xffffffffu, lsum, 2);
            if (gq == 0) {
                sM[r] = m_new;
                sL[r] = sL[r] * corr + lsum;
                sCr[r] = corr;
            }
        }
        __syncthreads();

        // ---- O = O*corr + P @ V ----
        #pragma unroll
        for (int i = 0; i < 4; i++) {
            float c_ = sCr[(ty << 2) + i];
            #pragma unroll
            for (int j = 0; j < 4; j++) oacc[i][j] *= c_;
        }
        #pragma unroll 4
        for (int j = 0; j < 64; j++) {
            int kd = (j >> 2) & 15;
            float4 vv = *(const float4*)&sV[j*64 + (((tx ^ kd)) << 2)];
            const float* vf = (const float*)&vv;
            #pragma unroll
            for (int i = 0; i < 4; i++) {
                float p = sP[((ty << 2) + i)*65 + j];
                #pragma unroll
                for (int jj = 0; jj < 4; jj++) oacc[i][jj] += p * vf[jj];
            }
        }
        __syncthreads();
    }

    // ---- normalize + write [B,S,H*dk] ----
    #pragma unroll
    for (int i = 0; i < 4; i++) {
        int r = (ty << 2) + i;
        float linv = 1.0f / sL[r];
        float4 o;
        o.x = oacc[i][0] * linv;
        o.y = oacc[i][1] * linv;
        o.z = oacc[i][2] * linv;
        o.w = oacc[i][3] * linv;
        *(float4*)&AO[((size_t)b * SSQ + i0 + r) * DDIM + h * DKK + (tx << 2)] = o;
    }
}

// ---------------- launch -------------------------------------------------
extern "C" void kernel_launch(void* const* d_in, const int* in_sizes, int n_in,
                              void* d_out, int out_size)
{
    const float* query  = (const float*)d_in[0];
    const float* key    = (const float*)d_in[1];
    const float* value  = (const float*)d_in[2];
    const float* key_pe = (const float*)d_in[3];
    const float* Wq = (const float*)d_in[4];
    const float* bq = (const float*)d_in[5];
    const float* Wk = (const float*)d_in[6];
    const float* bk = (const float*)d_in[7];
    const float* Wv = (const float*)d_in[8];
    const float* bv = (const float*)d_in[9];
    const float* Wo = (const float*)d_in[10];
    const float* bo = (const float*)d_in[11];
    (void)in_sizes; (void)n_in; (void)out_size;

    static float *gQ = nullptr, *gK = nullptr, *gV = nullptr, *gAO = nullptr;
    static bool inited = false;
    if (!inited) {
        cudaGetSymbolAddress((void**)&gQ,  g_Q);
        cudaGetSymbolAddress((void**)&gK,  g_K);
        cudaGetSymbolAddress((void**)&gV,  g_V);
        cudaGetSymbolAddress((void**)&gAO, g_AO);
        cudaFuncSetAttribute(attn_kernel,
                             cudaFuncAttributeMaxDynamicSharedMemorySize, AT_SMEM_BYTES);
        inited = true;
    }

    dim3 gblk(256);
    dim3 ggrid(DDIM / 128, (BB * SSQ) / 128);
    sgemm_bias<<<ggrid, gblk>>>(query, Wq, bq, gQ, BB*SSQ, DDIM, DDIM);
    sgemm_bias<<<ggrid, gblk>>>(key,   Wk, bk, gK, BB*SSQ, DDIM, DDIM);
    sgemm_bias<<<ggrid, gblk>>>(value, Wv, bv, gV, BB*SSQ, DDIM, DDIM);

    attn_kernel<<<dim3(SSQ / 64, BB * HH), gblk, AT_SMEM_BYTES>>>(gQ, gK, gV, key_pe, gAO);

    sgemm_bias<<<ggrid, gblk>>>(gAO, Wo, bo, (float*)d_out, BB*SSQ, DDIM, DDIM);
}

// round 5
// speedup vs baseline: 1.2152x; 1.2152x over previous
#include <cuda_runtime.h>
#include <cuda_bf16.h>
#include <cstdint>

#define BB  2
#define SSQ 2048
#define DDIM 1024
#define HH  16
#define DKK 64
#define MTOT (BB*SSQ)

// ---------------- scratch (static device, no allocations) ----------------
__device__ float g_Q [MTOT*DDIM];
__device__ float g_K [MTOT*DDIM];
__device__ float g_V [MTOT*DDIM];
__device__ float g_AO[MTOT*DDIM];
__device__ __nv_bfloat16 g_WhT[4][DDIM*DDIM];   // W^T hi-split, [N][K] K-major
__device__ __nv_bfloat16 g_WlT[4][DDIM*DDIM];   // W^T lo-split

// ---------------- helpers ------------------------------------------------
static __device__ __forceinline__ uint32_t smem_u32(const void* p) {
    uint32_t a;
    asm("{ .reg .u64 t; cvta.to.shared.u64 t, %1; cvt.u32.u64 %0, t; }"
        : "=r"(a) : "l"(p));
    return a;
}

#define LDSM_X4(r0, r1, r2, r3, addr) \
    asm volatile("ldmatrix.sync.aligned.m8n8.x4.shared.b16 {%0,%1,%2,%3}, [%4];" \
                 : "=r"(r0), "=r"(r1), "=r"(r2), "=r"(r3) : "r"(addr))

#define MMA_BF16(c, a, b0, b1) \
    asm volatile("mma.sync.aligned.m16n8k16.row.col.f32.bf16.bf16.f32 " \
                 "{%0,%1,%2,%3}, {%4,%5,%6,%7}, {%8,%9}, {%0,%1,%2,%3};" \
                 : "+f"((c)[0]), "+f"((c)[1]), "+f"((c)[2]), "+f"((c)[3]) \
                 : "r"((a)[0]), "r"((a)[1]), "r"((a)[2]), "r"((a)[3]), \
                   "r"(b0), "r"(b1))

// ---------------- W transpose + bf16 hi/lo split -------------------------
__global__ void wsplit_kernel(const float* __restrict__ W0, const float* __restrict__ W1,
                              const float* __restrict__ W2, const float* __restrict__ W3)
{
    __shared__ float t[32][33];
    const float* W = blockIdx.z == 0 ? W0 : blockIdx.z == 1 ? W1 : blockIdx.z == 2 ? W2 : W3;
    __nv_bfloat16* Wh = g_WhT[blockIdx.z];
    __nv_bfloat16* Wl = g_WlT[blockIdx.z];
    const int n0 = blockIdx.x * 32, k0 = blockIdx.y * 32;
    const int tx = threadIdx.x, ty = threadIdx.y;
    #pragma unroll
    for (int i = 0; i < 4; i++)
        t[ty + i*8][tx] = W[(size_t)(k0 + ty + i*8) * DDIM + n0 + tx];
    __syncthreads();
    #pragma unroll
    for (int i = 0; i < 4; i++) {
        float x = t[tx][ty + i*8];
        __nv_bfloat16 h = __float2bfloat16_rn(x);
        __nv_bfloat16 l = __float2bfloat16_rn(x - __bfloat162float(h));
        size_t o = (size_t)(n0 + ty + i*8) * DDIM + k0 + tx;
        Wh[o] = h; Wl[o] = l;
    }
}

// ---------------- mma.sync bf16x3 projection GEMM ------------------------
// C[4096,1024] = A(fp32)@W + bias via Ah*Wh + Ah*Wl + Al*Wh  (fp32 accum)
// CTA 128x128, K staged 64/iter. 8 warps (2 M x 4 N), warp tile 64x32.
// smem pitch = 72 bf16 (144B): 16B-aligned rows, conflict-free ldmatrix.
#define PITCH    72
#define PITCHB   144
#define TILE_B   (128 * PITCHB)          // 18432 bytes per buffer
#define OFF_AH   0
#define OFF_AL   TILE_B
#define OFF_WH   (2 * TILE_B)
#define OFF_WL   (3 * TILE_B)
#define PJ_SMEM  (4 * TILE_B)            // 73728 bytes

__device__ __forceinline__ void proj_mma_body(
    const float* __restrict__ A, const __nv_bfloat16* __restrict__ WhT,
    const __nv_bfloat16* __restrict__ WlT, const float* __restrict__ bias,
    float* __restrict__ C)
{
    extern __shared__ char smem[];
    const uint32_t sbase = smem_u32(smem);
    const int tid = threadIdx.x;
    const int lane = tid & 31, wid = tid >> 5;
    const int wm = wid & 1, wn = wid >> 1;          // warp grid 2 x 4
    const int bn = blockIdx.x << 7, bm = blockIdx.y << 7;

    float acc[16][4];
    #pragma unroll
    for (int i = 0; i < 16; i++)
        #pragma unroll
        for (int j = 0; j < 4; j++) acc[i][j] = 0.f;

    // global-load lane mapping: 2 threads per row, 32 cols each
    const int gr = tid >> 1;                 // row 0..127
    const int gc = (tid & 1) << 5;           // col 0 or 32

    float4 av[8];
    uint4  whv[4], wlv[4];

    // ---- prefetch k-tile 0 ----
    {
        const float* ap = A + (size_t)(bm + gr) * DDIM + gc;
        #pragma unroll
        for (int j = 0; j < 8; j++) av[j] = *(const float4*)(ap + j*4);
        const __nv_bfloat16* hp = WhT + (size_t)(bn + gr) * DDIM + gc;
        const __nv_bfloat16* lp = WlT + (size_t)(bn + gr) * DDIM + gc;
        #pragma unroll
        for (int j = 0; j < 4; j++) {
            whv[j] = *(const uint4*)(hp + j*8);
            wlv[j] = *(const uint4*)(lp + j*8);
        }
    }

    // ldmatrix lane-derived address components
    const uint32_t a_base = sbase + (uint32_t)(((wm << 6) + (lane & 15)) * PITCHB)
                          + ((lane >> 4) << 4);
    const int b_n   = (lane & 7) + ((lane >> 4) << 3);
    const uint32_t b_base = sbase + (uint32_t)(((wn << 5) + b_n) * PITCHB)
                          + ((((lane >> 3) & 1) << 3) << 1);

    for (int kt = 0; kt < 16; kt++) {
        // ---- store prefetched tile to smem (convert/split A) ----
        {
            char* rowA = smem + (size_t)gr * PITCHB + gc * 2;
            #pragma unroll
            for (int j = 0; j < 8; j++) {
                float4 v = av[j];
                __nv_bfloat16 h0 = __float2bfloat16_rn(v.x);
                __nv_bfloat16 h1 = __float2bfloat16_rn(v.y);
                __nv_bfloat16 h2 = __float2bfloat16_rn(v.z);
                __nv_bfloat16 h3 = __float2bfloat16_rn(v.w);
                __nv_bfloat16 l0 = __float2bfloat16_rn(v.x - __bfloat162float(h0));
                __nv_bfloat16 l1 = __float2bfloat16_rn(v.y - __bfloat162float(h1));
                __nv_bfloat16 l2 = __float2bfloat16_rn(v.z - __bfloat162float(h2));
                __nv_bfloat16 l3 = __float2bfloat16_rn(v.w - __bfloat162float(h3));
                uint2 uh, ul;
                uh.x = ((uint32_t)__bfloat16_as_ushort(h1) << 16) | __bfloat16_as_ushort(h0);
                uh.y = ((uint32_t)__bfloat16_as_ushort(h3) << 16) | __bfloat16_as_ushort(h2);
                ul.x = ((uint32_t)__bfloat16_as_ushort(l1) << 16) | __bfloat16_as_ushort(l0);
                ul.y = ((uint32_t)__bfloat16_as_ushort(l3) << 16) | __bfloat16_as_ushort(l2);
                *(uint2*)(rowA + OFF_AH + j*8) = uh;
                *(uint2*)(rowA + OFF_AL + j*8) = ul;
            }
            char* rowW = smem + (size_t)gr * PITCHB + gc * 2;
            #pragma unroll
            for (int j = 0; j < 4; j++) {
                *(uint4*)(rowW + OFF_WH + j*16) = whv[j];
                *(uint4*)(rowW + OFF_WL + j*16) = wlv[j];
            }
        }
        __syncthreads();

        // ---- prefetch next k-tile while computing this one ----
        if (kt < 15) {
            const int k0 = (kt + 1) << 6;
            const float* ap = A + (size_t)(bm + gr) * DDIM + k0 + gc;
            #pragma unroll
            for (int j = 0; j < 8; j++) av[j] = *(const float4*)(ap + j*4);
            const __nv_bfloat16* hp = WhT + (size_t)(bn + gr) * DDIM + k0 + gc;
            const __nv_bfloat16* lp = WlT + (size_t)(bn + gr) * DDIM + k0 + gc;
            #pragma unroll
            for (int j = 0; j < 4; j++) {
                whv[j] = *(const uint4*)(hp + j*8);
                wlv[j] = *(const uint4*)(lp + j*8);
            }
        }

        // ---- compute: 4 k16 steps ----
        #pragma unroll
        for (int ks = 0; ks < 4; ks++) {
            uint32_t ah[4][4], al[4][4];
            #pragma unroll
            for (int mt = 0; mt < 4; mt++) {
                uint32_t ad = a_base + (uint32_t)(mt * 16 * PITCHB) + (ks << 5);
                LDSM_X4(ah[mt][0], ah[mt][1], ah[mt][2], ah[mt][3], ad + OFF_AH);
                LDSM_X4(al[mt][0], al[mt][1], al[mt][2], al[mt][3], ad + OFF_AL);
            }
            uint32_t bh[2][4], bl[2][4];
            #pragma unroll
            for (int pr = 0; pr < 2; pr++) {
                uint32_t bd = b_base + (uint32_t)(pr * 16 * PITCHB) + (ks << 5);
                LDSM_X4(bh[pr][0], bh[pr][1], bh[pr][2], bh[pr][3], bd + OFF_WH);
                LDSM_X4(bl[pr][0], bl[pr][1], bl[pr][2], bl[pr][3], bd + OFF_WL);
            }
            #pragma unroll
            for (int mt = 0; mt < 4; mt++)
                #pragma unroll
                for (int nt = 0; nt < 4; nt++) {
                    const int pr = nt >> 1, f = (nt & 1) << 1;
                    float* c = acc[mt*4 + nt];
                    MMA_BF16(c, ah[mt], bh[pr][f], bh[pr][f+1]);
                    MMA_BF16(c, ah[mt], bl[pr][f], bl[pr][f+1]);
                    MMA_BF16(c, al[mt], bh[pr][f], bh[pr][f+1]);
                }
        }
        __syncthreads();
    }

    // ---- epilogue: accum + bias -> C ----
    const int g = lane >> 2, tg = lane & 3;
    #pragma unroll
    for (int mt = 0; mt < 4; mt++) {
        const int row0 = bm + (wm << 6) + mt*16 + g;
        #pragma unroll
        for (int nt = 0; nt < 4; nt++) {
            const int col = bn + (wn << 5) + nt*8 + (tg << 1);
            const float* c = acc[mt*4 + nt];
            float b0 = bias[col], b1 = bias[col + 1];
            float2 o0, o1;
            o0.x = c[0] + b0; o0.y = c[1] + b1;
            o1.x = c[2] + b0; o1.y = c[3] + b1;
            *(float2*)(C + (size_t)row0 * DDIM + col)       = o0;
            *(float2*)(C + (size_t)(row0 + 8) * DDIM + col) = o1;
        }
    }
}

__global__ __launch_bounds__(256, 1)
void proj_qkv_tc(const float* __restrict__ q, const float* __restrict__ k,
                 const float* __restrict__ v, const float* __restrict__ bq,
                 const float* __restrict__ bk, const float* __restrict__ bv)
{
    const int z = blockIdx.z;
    const float* A    = z == 0 ? q  : z == 1 ? k  : v;
    const float* bias = z == 0 ? bq : z == 1 ? bk : bv;
    float* C          = z == 0 ? g_Q : z == 1 ? g_K : g_V;
    proj_mma_body(A, g_WhT[z], g_WlT[z], bias, C);
}

__global__ __launch_bounds__(256, 1)
void proj_o_tc(const float* __restrict__ bo, float* __restrict__ out)
{
    proj_mma_body(g_AO, g_WhT[3], g_WlT[3], bo, out);
}

// ---------------- flash attention with relative-position bias ------------
#define AT_SMEM_FLOATS 37120
#define AT_SMEM_BYTES  (AT_SMEM_FLOATS * 4)

__global__ __launch_bounds__(256, 1)
void attn_kernel(const float* __restrict__ Qg, const float* __restrict__ Kg,
                 const float* __restrict__ Vg, const float* __restrict__ pe,
                 float* __restrict__ AO)
{
    extern __shared__ float sm[];
    float* sQT  = sm;
    float* sKP  = sm + 4096;
    float* sV   = sm + 16384;
    float* sAll = sm + 20480;
    float* sP   = sm + 32768;
    float* sM   = sm + 36928;
    float* sL   = sm + 36992;
    float* sCr  = sm + 37056;

    const int tid = threadIdx.x;
    const int tx = tid & 15, ty = tid >> 4;
    const int i0 = (gridDim.x - 1 - blockIdx.x) << 6;
    const int bh = blockIdx.y;
    const int b = bh >> 4, h = bh & 15;
    const float scale = 0.125f;

    const float* Qb = Qg + (size_t)b * SSQ * DDIM + h * DKK;
    const float* Kb = Kg + (size_t)b * SSQ * DDIM + h * DKK;
    const float* Vb = Vg + (size_t)b * SSQ * DDIM + h * DKK;

    #pragma unroll
    for (int it = 0; it < 4; it++) {
        int e = (tid << 2) + (it << 10);
        int r = e >> 6, d4 = e & 63;
        float4 q = *(const float4*)&Qb[(size_t)(i0 + r) * DDIM + d4];
        sQT[(d4+0)*64 + r] = q.x;
        sQT[(d4+1)*64 + r] = q.y;
        sQT[(d4+2)*64 + r] = q.z;
        sQT[(d4+3)*64 + r] = q.w;
    }
    if (tid < 64) { sM[tid] = -1e30f; sL[tid] = 0.f; }

    float oacc[4][4];
    #pragma unroll
    for (int i = 0; i < 4; i++)
        #pragma unroll
        for (int j = 0; j < 4; j++) oacc[i][j] = 0.f;

    __syncthreads();

    const int ntiles = (i0 >> 6) + 1;
    for (int kt = 0; kt < ntiles; kt++) {
        const int j0 = kt << 6;
        const int base0 = SSQ - 64 - i0 + j0;

        #pragma unroll
        for (int it = 0; it < 4; it++) {
            int e = (tid << 2) + (it << 10);
            int c = e >> 6, d4 = e & 63;
            float4 kv = *(const float4*)&Kb[(size_t)(j0 + c) * DDIM + d4];
            int g = c >> 2, cc = c & 3;
            #pragma unroll
            for (int q = 0; q < 4; q++) {
                int d = d4 + q;
                int pg = g ^ ((d >> 2) & 15);
                sKP[d*192 + (pg << 2) + cc] = ((const float*)&kv)[q];
            }
        }
        #pragma unroll
        for (int it = 0; it < 8; it++) {
            int idx = tid + (it << 8);
            if (idx < 2032) {
                int off = idx >> 4;
                int d4 = (idx & 15) << 2;
                int l = base0 + off;
                l = l < 0 ? 0 : (l > SSQ - 1 ? SSQ - 1 : l);
                float4 pv = *(const float4*)&pe[l * DKK + d4];
                int g = (64 + off) >> 2, cc = off & 3;
                #pragma unroll
                for (int q = 0; q < 4; q++) {
                    int d = d4 + q;
                    int pg = (g & 48) | ((g & 15) ^ ((d >> 2) & 15));
                    sKP[d*192 + (pg << 2) + cc] = ((const float*)&pv)[q];
                }
            }
        }
        #pragma unroll
        for (int it = 0; it < 4; it++) {
            int e = (tid << 2) + (it << 10);
            int j = e >> 6, c4 = e & 63;
            float4 vv = *(const float4*)&Vb[(size_t)(j0 + j) * DDIM + c4];
            int pg = (c4 >> 2) ^ ((j >> 2) & 15);
            *(float4*)&sV[j*64 + (pg << 2)] = vv;
        }
        __syncthreads();

        float sc[4][12];
        #pragma unroll
        for (int i = 0; i < 4; i++)
            #pragma unroll
            for (int j = 0; j < 12; j++) sc[i][j] = 0.f;

        #pragma unroll 4
        for (int d = 0; d < 64; d++) {
            int kd = (d >> 2) & 15;
            float4 qv = *(const float4*)&sQT[d*64 + (ty << 2)];
            int xg = tx ^ kd;
            float4 k0 = *(const float4*)&sKP[d*192 + (xg << 2)];
            float4 k1 = *(const float4*)&sKP[d*192 + ((16 | xg) << 2)];
            float4 k2 = *(const float4*)&sKP[d*192 + ((32 | xg) << 2)];
            const float* qf  = (const float*)&qv;
            const float* f0  = (const float*)&k0;
            const float* f1  = (const float*)&k1;
            const float* f2  = (const float*)&k2;
            #pragma unroll
            for (int i = 0; i < 4; i++) {
                float q_ = qf[i];
                #pragma unroll
                for (int j = 0; j < 4; j++) {
                    sc[i][j]     += q_ * f0[j];
                    sc[i][4 + j] += q_ * f1[j];
                    sc[i][8 + j] += q_ * f2[j];
                }
            }
        }
        #pragma unroll
        for (int i = 0; i < 4; i++) {
            int r = (ty << 2) + i;
            #pragma unroll
            for (int w = 0; w < 3; w++)
                #pragma unroll
                for (int j = 0; j < 4; j++)
                    sAll[r*192 + (w << 6) + (tx << 2) + j] = sc[i][(w << 2) + j];
        }
        __syncthreads();

        {
            int r = tid >> 2, gq = tid & 3;
            int gi = i0 + r;
            float m_old = sM[r];
            float vmax = -1e30f;
            float vals[16];
            #pragma unroll
            for (int kk = 0; kk < 16; kk++) {
                int c = gq + (kk << 2);
                float s;
                if (j0 + c <= gi) {
                    int off = c - r + 63;
                    s = (sAll[r*192 + c] + sAll[r*192 + 64 + off]) * scale;
                } else s = -1e30f;
                vals[kk] = s;
                vmax = fmaxf(vmax, s);
            }
            vmax = fmaxf(vmax, __shfl_xor_sync(0xffffffffu, vmax, 1));
            vmax = fmaxf(vmax, __shfl_xor_sync(0xffffffffu, vmax, 2));
            float m_new = fmaxf(m_old, vmax);
            float corr = __expf(m_old - m_new);
            float lsum = 0.f;
            #pragma unroll
            for (int kk = 0; kk < 16; kk++) {
                float p = __expf(vals[kk] - m_new);
                lsum += p;
                sP[r*65 + gq + (kk << 2)] = p;
            }
            lsum += __shfl_xor_sync(0xffffffffu, lsum, 1);
            lsum += __shfl_xor_sync(0xffffffffu, lsum, 2);
            if (gq == 0) {
                sM[r] = m_new;
                sL[r] = sL[r] * corr + lsum;
                sCr[r] = corr;
            }
        }
        __syncthreads();

        #pragma unroll
        for (int i = 0; i < 4; i++) {
            float c_ = sCr[(ty << 2) + i];
            #pragma unroll
            for (int j = 0; j < 4; j++) oacc[i][j] *= c_;
        }
        #pragma unroll 4
        for (int j = 0; j < 64; j++) {
            int kd = (j >> 2) & 15;
            float4 vv = *(const float4*)&sV[j*64 + (((tx ^ kd)) << 2)];
            const float* vf = (const float*)&vv;
            #pragma unroll
            for (int i = 0; i < 4; i++) {
                float p = sP[((ty << 2) + i)*65 + j];
                #pragma unroll
                for (int jj = 0; jj < 4; jj++) oacc[i][jj] += p * vf[jj];
            }
        }
        __syncthreads();
    }

    #pragma unroll
    for (int i = 0; i < 4; i++) {
        int r = (ty << 2) + i;
        float linv = 1.0f / sL[r];
        float4 o;
        o.x = oacc[i][0] * linv;
        o.y = oacc[i][1] * linv;
        o.z = oacc[i][2] * linv;
        o.w = oacc[i][3] * linv;
        *(float4*)&AO[((size_t)b * SSQ + i0 + r) * DDIM + h * DKK + (tx << 2)] = o;
    }
}

// ---------------- launch -------------------------------------------------
extern "C" void kernel_launch(void* const* d_in, const int* in_sizes, int n_in,
                              void* d_out, int out_size)
{
    const float* query  = (const float*)d_in[0];
    const float* key    = (const float*)d_in[1];
    const float* value  = (const float*)d_in[2];
    const float* key_pe = (const float*)d_in[3];
    const float* Wq = (const float*)d_in[4];
    const float* bq = (const float*)d_in[5];
    const float* Wk = (const float*)d_in[6];
    const float* bk = (const float*)d_in[7];
    const float* Wv = (const float*)d_in[8];
    const float* bv = (const float*)d_in[9];
    const float* Wo = (const float*)d_in[10];
    const float* bo = (const float*)d_in[11];
    (void)in_sizes; (void)n_in; (void)out_size;

    static float *gQ = nullptr, *gK = nullptr, *gV = nullptr, *gAO = nullptr;
    static bool inited = false;
    if (!inited) {
        cudaGetSymbolAddress((void**)&gQ,  g_Q);
        cudaGetSymbolAddress((void**)&gK,  g_K);
        cudaGetSymbolAddress((void**)&gV,  g_V);
        cudaGetSymbolAddress((void**)&gAO, g_AO);
        cudaFuncSetAttribute(attn_kernel,
                             cudaFuncAttributeMaxDynamicSharedMemorySize, AT_SMEM_BYTES);
        cudaFuncSetAttribute(proj_qkv_tc,
                             cudaFuncAttributeMaxDynamicSharedMemorySize, PJ_SMEM);
        cudaFuncSetAttribute(proj_o_tc,
                             cudaFuncAttributeMaxDynamicSharedMemorySize, PJ_SMEM);
        inited = true;
    }

    // 1. transpose + split all four W matrices into bf16 hi/lo
    wsplit_kernel<<<dim3(32, 32, 4), dim3(32, 8)>>>(Wq, Wk, Wv, Wo);

    // 2. Q/K/V projections on tensor cores (mma.sync bf16x3)
    proj_qkv_tc<<<dim3(8, 32, 3), 256, PJ_SMEM>>>(query, key, value, bq, bk, bv);

    // 3. attention
    attn_kernel<<<dim3(SSQ / 64, BB * HH), 256, AT_SMEM_BYTES>>>(gQ, gK, gV, key_pe, gAO);

    // 4. output projection on tensor cores
    proj_o_tc<<<dim3(8, 32, 1), 256, PJ_SMEM>>>(bo, (float*)d_out);
}

// round 7
// speedup vs baseline: 1.6604x; 1.3664x over previous
#include <cuda_runtime.h>
#include <cuda_bf16.h>
#include <cstdint>

#define BB  2
#define SSQ 2048
#define DDIM 1024
#define HH  16
#define DKK 64
#define MTOT (BB*SSQ)

// ---------------- scratch (static device, no allocations) ----------------
__device__ float g_Q [MTOT*DDIM];
__device__ float g_K [MTOT*DDIM];
__device__ float g_V [MTOT*DDIM];
__device__ float g_AO[MTOT*DDIM];
__device__ __nv_bfloat16 g_WhT[4][DDIM*DDIM];   // W^T hi-split, [N][K] K-major
__device__ __nv_bfloat16 g_WlT[4][DDIM*DDIM];   // W^T lo-split

// ---------------- helpers ------------------------------------------------
static __device__ __forceinline__ uint32_t smem_u32(const void* p) {
    uint32_t a;
    asm("{ .reg .u64 t; cvta.to.shared.u64 t, %1; cvt.u32.u64 %0, t; }"
        : "=r"(a) : "l"(p));
    return a;
}

#define LDSM_X4(r0, r1, r2, r3, addr) \
    asm volatile("ldmatrix.sync.aligned.m8n8.x4.shared.b16 {%0,%1,%2,%3}, [%4];" \
                 : "=r"(r0), "=r"(r1), "=r"(r2), "=r"(r3) : "r"(addr))

#define MMA_BF16(c, a, b0, b1) \
    asm volatile("mma.sync.aligned.m16n8k16.row.col.f32.bf16.bf16.f32 " \
                 "{%0,%1,%2,%3}, {%4,%5,%6,%7}, {%8,%9}, {%0,%1,%2,%3};" \
                 : "+f"((c)[0]), "+f"((c)[1]), "+f"((c)[2]), "+f"((c)[3]) \
                 : "r"((a)[0]), "r"((a)[1]), "r"((a)[2]), "r"((a)[3]), \
                   "r"(b0), "r"(b1))

static __device__ __forceinline__ void split4(float4 v, uint2& h, uint2& l) {
    __nv_bfloat16 h0 = __float2bfloat16_rn(v.x);
    __nv_bfloat16 h1 = __float2bfloat16_rn(v.y);
    __nv_bfloat16 h2 = __float2bfloat16_rn(v.z);
    __nv_bfloat16 h3 = __float2bfloat16_rn(v.w);
    __nv_bfloat16 l0 = __float2bfloat16_rn(v.x - __bfloat162float(h0));
    __nv_bfloat16 l1 = __float2bfloat16_rn(v.y - __bfloat162float(h1));
    __nv_bfloat16 l2 = __float2bfloat16_rn(v.z - __bfloat162float(h2));
    __nv_bfloat16 l3 = __float2bfloat16_rn(v.w - __bfloat162float(h3));
    h.x = ((uint32_t)__bfloat16_as_ushort(h1) << 16) | __bfloat16_as_ushort(h0);
    h.y = ((uint32_t)__bfloat16_as_ushort(h3) << 16) | __bfloat16_as_ushort(h2);
    l.x = ((uint32_t)__bfloat16_as_ushort(l1) << 16) | __bfloat16_as_ushort(l0);
    l.y = ((uint32_t)__bfloat16_as_ushort(l3) << 16) | __bfloat16_as_ushort(l2);
}

// ---------------- W transpose + bf16 hi/lo split -------------------------
__global__ void wsplit_kernel(const float* __restrict__ W0, const float* __restrict__ W1,
                              const float* __restrict__ W2, const float* __restrict__ W3)
{
    __shared__ float t[32][33];
    const float* W = blockIdx.z == 0 ? W0 : blockIdx.z == 1 ? W1 : blockIdx.z == 2 ? W2 : W3;
    __nv_bfloat16* Wh = g_WhT[blockIdx.z];
    __nv_bfloat16* Wl = g_WlT[blockIdx.z];
    const int n0 = blockIdx.x * 32, k0 = blockIdx.y * 32;
    const int tx = threadIdx.x, ty = threadIdx.y;
    #pragma unroll
    for (int i = 0; i < 4; i++)
        t[ty + i*8][tx] = W[(size_t)(k0 + ty + i*8) * DDIM + n0 + tx];
    __syncthreads();
    #pragma unroll
    for (int i = 0; i < 4; i++) {
        float x = t[tx][ty + i*8];
        __nv_bfloat16 h = __float2bfloat16_rn(x);
        __nv_bfloat16 l = __float2bfloat16_rn(x - __bfloat162float(h));
        size_t o = (size_t)(n0 + ty + i*8) * DDIM + k0 + tx;
        Wh[o] = h; Wl[o] = l;
    }
}

// ---------------- mma.sync bf16x3 projection GEMM ------------------------
#define PITCH    72
#define PITCHB   144
#define TILE_B   (128 * PITCHB)
#define OFF_AH   0
#define OFF_AL   TILE_B
#define OFF_WH   (2 * TILE_B)
#define OFF_WL   (3 * TILE_B)
#define PJ_SMEM  (4 * TILE_B)

__device__ __forceinline__ void proj_mma_body(
    const float* __restrict__ A, const __nv_bfloat16* __restrict__ WhT,
    const __nv_bfloat16* __restrict__ WlT, const float* __restrict__ bias,
    float* __restrict__ C)
{
    extern __shared__ char smem[];
    const uint32_t sbase = smem_u32(smem);
    const int tid = threadIdx.x;
    const int lane = tid & 31, wid = tid >> 5;
    const int wm = wid & 1, wn = wid >> 1;
    const int bn = blockIdx.x << 7, bm = blockIdx.y << 7;

    float acc[16][4];
    #pragma unroll
    for (int i = 0; i < 16; i++)
        #pragma unroll
        for (int j = 0; j < 4; j++) acc[i][j] = 0.f;

    const int gr = tid >> 1;
    const int gc = (tid & 1) << 5;

    float4 av[8];
    uint4  whv[4], wlv[4];

    {
        const float* ap = A + (size_t)(bm + gr) * DDIM + gc;
        #pragma unroll
        for (int j = 0; j < 8; j++) av[j] = *(const float4*)(ap + j*4);
        const __nv_bfloat16* hp = WhT + (size_t)(bn + gr) * DDIM + gc;
        const __nv_bfloat16* lp = WlT + (size_t)(bn + gr) * DDIM + gc;
        #pragma unroll
        for (int j = 0; j < 4; j++) {
            whv[j] = *(const uint4*)(hp + j*8);
            wlv[j] = *(const uint4*)(lp + j*8);
        }
    }

    const uint32_t a_base = sbase + (uint32_t)(((wm << 6) + (lane & 15)) * PITCHB)
                          + ((lane >> 4) << 4);
    const int b_n   = (lane & 7) + ((lane >> 4) << 3);
    const uint32_t b_base = sbase + (uint32_t)(((wn << 5) + b_n) * PITCHB)
                          + ((((lane >> 3) & 1) << 3) << 1);

    for (int kt = 0; kt < 16; kt++) {
        {
            char* rowA = smem + (size_t)gr * PITCHB + gc * 2;
            #pragma unroll
            for (int j = 0; j < 8; j++) {
                uint2 uh, ul;
                split4(av[j], uh, ul);
                *(uint2*)(rowA + OFF_AH + j*8) = uh;
                *(uint2*)(rowA + OFF_AL + j*8) = ul;
            }
            char* rowW = smem + (size_t)gr * PITCHB + gc * 2;
            #pragma unroll
            for (int j = 0; j < 4; j++) {
                *(uint4*)(rowW + OFF_WH + j*16) = whv[j];
                *(uint4*)(rowW + OFF_WL + j*16) = wlv[j];
            }
        }
        __syncthreads();

        if (kt < 15) {
            const int k0 = (kt + 1) << 6;
            const float* ap = A + (size_t)(bm + gr) * DDIM + k0 + gc;
            #pragma unroll
            for (int j = 0; j < 8; j++) av[j] = *(const float4*)(ap + j*4);
            const __nv_bfloat16* hp = WhT + (size_t)(bn + gr) * DDIM + k0 + gc;
            const __nv_bfloat16* lp = WlT + (size_t)(bn + gr) * DDIM + k0 + gc;
            #pragma unroll
            for (int j = 0; j < 4; j++) {
                whv[j] = *(const uint4*)(hp + j*8);
                wlv[j] = *(const uint4*)(lp + j*8);
            }
        }

        #pragma unroll
        for (int ks = 0; ks < 4; ks++) {
            uint32_t ah[4][4], al[4][4];
            #pragma unroll
            for (int mt = 0; mt < 4; mt++) {
                uint32_t ad = a_base + (uint32_t)(mt * 16 * PITCHB) + (ks << 5);
                LDSM_X4(ah[mt][0], ah[mt][1], ah[mt][2], ah[mt][3], ad + OFF_AH);
                LDSM_X4(al[mt][0], al[mt][1], al[mt][2], al[mt][3], ad + OFF_AL);
            }
            uint32_t bh[2][4], bl[2][4];
            #pragma unroll
            for (int pr = 0; pr < 2; pr++) {
                uint32_t bd = b_base + (uint32_t)(pr * 16 * PITCHB) + (ks << 5);
                LDSM_X4(bh[pr][0], bh[pr][1], bh[pr][2], bh[pr][3], bd + OFF_WH);
                LDSM_X4(bl[pr][0], bl[pr][1], bl[pr][2], bl[pr][3], bd + OFF_WL);
            }
            #pragma unroll
            for (int mt = 0; mt < 4; mt++)
                #pragma unroll
                for (int nt = 0; nt < 4; nt++) {
                    const int pr = nt >> 1, f = (nt & 1) << 1;
                    float* c = acc[mt*4 + nt];
                    MMA_BF16(c, ah[mt], bh[pr][f], bh[pr][f+1]);
                    MMA_BF16(c, ah[mt], bl[pr][f], bl[pr][f+1]);
                    MMA_BF16(c, al[mt], bh[pr][f], bh[pr][f+1]);
                }
        }
        __syncthreads();
    }

    const int g = lane >> 2, tg = lane & 3;
    #pragma unroll
    for (int mt = 0; mt < 4; mt++) {
        const int row0 = bm + (wm << 6) + mt*16 + g;
        #pragma unroll
        for (int nt = 0; nt < 4; nt++) {
            const int col = bn + (wn << 5) + nt*8 + (tg << 1);
            const float* c = acc[mt*4 + nt];
            float b0 = bias[col], b1 = bias[col + 1];
            float2 o0, o1;
            o0.x = c[0] + b0; o0.y = c[1] + b1;
            o1.x = c[2] + b0; o1.y = c[3] + b1;
            *(float2*)(C + (size_t)row0 * DDIM + col)       = o0;
            *(float2*)(C + (size_t)(row0 + 8) * DDIM + col) = o1;
        }
    }
}

__global__ __launch_bounds__(256, 1)
void proj_qkv_tc(const float* __restrict__ q, const float* __restrict__ k,
                 const float* __restrict__ v, const float* __restrict__ bq,
                 const float* __restrict__ bk, const float* __restrict__ bv)
{
    const int z = blockIdx.z;
    const float* A    = z == 0 ? q  : z == 1 ? k  : v;
    const float* bias = z == 0 ? bq : z == 1 ? bk : bv;
    float* C          = z == 0 ? g_Q : z == 1 ? g_K : g_V;
    proj_mma_body(A, g_WhT[z], g_WlT[z], bias, C);
}

__global__ __launch_bounds__(256, 1)
void proj_o_tc(const float* __restrict__ bo, float* __restrict__ out)
{
    proj_mma_body(g_AO, g_WhT[3], g_WlT[3], bo, out);
}

// ---------------- mma.sync flash attention with relative bias ------------
// 64-query tile per CTA, 8 warps. Per j-tile:
//   score: [Q | bf16x3] @ [Ktile(64) ; PEwin(128)]^T -> sAll fp32 (64x192)
//   SIMT online softmax -> P bf16 hi/lo
//   PV: P @ V (V transposed to d-major) bf16x3, O in registers
// smem byte offsets (all bf16 tiles pitch 144B = 72 elems):
#define AOFF_QH   0
#define AOFF_QL   9216
#define AOFF_KPH  18432      // 192 rows
#define AOFF_KPL  46080
#define AOFF_VTH  73728
#define AOFF_VTL  82944
#define AOFF_PH   92160
#define AOFF_PL   101376
#define AOFF_ALL  110592     // fp32 64 x 196
#define AOFF_M    160768
#define AOFF_L    161024
#define AOFF_CR   161280
#define AT2_SMEM  161792
#define SALL_P    196

__global__ __launch_bounds__(256, 1)
void attn_mma(const float* __restrict__ Qg, const float* __restrict__ Kg,
              const float* __restrict__ Vg, const float* __restrict__ pe,
              float* __restrict__ AO)
{
    extern __shared__ char smem[];
    const uint32_t sb = smem_u32(smem);
    float* sAll = (float*)(smem + AOFF_ALL);
    float* sM   = (float*)(smem + AOFF_M);
    float* sL   = (float*)(smem + AOFF_L);
    float* sCr  = (float*)(smem + AOFF_CR);

    const int tid = threadIdx.x;
    const int lane = tid & 31, wid = tid >> 5;
    const int wm = wid & 3, wn = wid >> 2;       // 4m x 2n
    const int i0 = (gridDim.x - 1 - blockIdx.x) << 6;
    const int bh = blockIdx.y;
    const int b = bh >> 4, h = bh & 15;
    const float scale = 0.125f;

    const float* Qb = Qg + (size_t)b * SSQ * DDIM + h * DKK;
    const float* Kb = Kg + (size_t)b * SSQ * DDIM + h * DKK;
    const float* Vb = Vg + (size_t)b * SSQ * DDIM + h * DKK;

    // load/split mappings
    const int ld_r  = tid >> 2;              // 0..63
    const int ld_db = (tid & 3) << 4;        // 0,16,32,48
    const int pe_r  = tid >> 1;              // 0..127
    const int pe_db = (tid & 1) << 5;        // 0,32

    // ---- Q tile load + split (once) ----
    {
        const float* qp = Qb + (size_t)(i0 + ld_r) * DDIM + ld_db;
        char* dst = smem + ld_r * PITCHB + ld_db * 2;
        #pragma unroll
        for (int j = 0; j < 4; j++) {
            uint2 uh, ul;
            split4(*(const float4*)(qp + j*4), uh, ul);
            *(uint2*)(dst + AOFF_QH + j*8) = uh;
            *(uint2*)(dst + AOFF_QL + j*8) = ul;
        }
    }
    if (tid < 64) { sM[tid] = -1e30f; sL[tid] = 0.f; }

    float oacc[4][4];
    #pragma unroll
    for (int i = 0; i < 4; i++)
        #pragma unroll
        for (int j = 0; j < 4; j++) oacc[i][j] = 0.f;

    // ldmatrix lane bases
    const uint32_t a_off = (uint32_t)(((wm << 4) + (lane & 15)) * PITCHB)
                         + ((lane >> 4) << 4);
    const int b_n = (lane & 7) + ((lane >> 4) << 3);
    const uint32_t b_byte = ((lane >> 3) & 1) << 4;

    const int g = lane >> 2, tg = lane & 3;
    const int ntiles = (i0 >> 6) + 1;

    for (int kt = 0; kt < ntiles; kt++) {
        const int j0 = kt << 6;
        const int base0 = SSQ - 64 - i0 + j0;

        // ---- loads: K rows 0..63 of KP, V transposed, PE rows 64..191 ----
        {
            const float* kp = Kb + (size_t)(j0 + ld_r) * DDIM + ld_db;
            char* dstk = smem + ld_r * PITCHB + ld_db * 2;
            #pragma unroll
            for (int j = 0; j < 4; j++) {
                uint2 uh, ul;
                split4(*(const float4*)(kp + j*4), uh, ul);
                *(uint2*)(dstk + AOFF_KPH + j*8) = uh;
                *(uint2*)(dstk + AOFF_KPL + j*8) = ul;
            }
            const float* vp = Vb + (size_t)(j0 + ld_r) * DDIM + ld_db;
            #pragma unroll
            for (int j = 0; j < 4; j++) {
                float4 v = *(const float4*)(vp + j*4);
                #pragma unroll
                for (int q = 0; q < 4; q++) {
                    float x = ((const float*)&v)[q];
                    __nv_bfloat16 hh = __float2bfloat16_rn(x);
                    __nv_bfloat16 ll = __float2bfloat16_rn(x - __bfloat162float(hh));
                    int d = ld_db + j*4 + q;
                    *(ushort*)(smem + AOFF_VTH + d * PITCHB + ld_r * 2) = __bfloat16_as_ushort(hh);
                    *(ushort*)(smem + AOFF_VTL + d * PITCHB + ld_r * 2) = __bfloat16_as_ushort(ll);
                }
            }
            int l = base0 + pe_r;
            l = l < 0 ? 0 : (l > SSQ - 1 ? SSQ - 1 : l);
            const float* pep = pe + l * DKK + pe_db;
            char* dstp = smem + (64 + pe_r) * PITCHB + pe_db * 2;
            #pragma unroll
            for (int j = 0; j < 8; j++) {
                uint2 uh, ul;
                split4(*(const float4*)(pep + j*4), uh, ul);
                *(uint2*)(dstp + AOFF_KPH + j*8) = uh;
                *(uint2*)(dstp + AOFF_KPL + j*8) = ul;
            }
        }
        __syncthreads();

        // ---- score GEMM: warp = m16 x n96 over [K|PE] ----
        {
            float acc[12][4];
            #pragma unroll
            for (int i = 0; i < 12; i++)
                #pragma unroll
                for (int j = 0; j < 4; j++) acc[i][j] = 0.f;

            #pragma unroll
            for (int ks = 0; ks < 4; ks++) {
                uint32_t ah[4], al[4];
                const uint32_t ad = sb + a_off + (ks << 5);
                LDSM_X4(ah[0], ah[1], ah[2], ah[3], ad + AOFF_QH);
                LDSM_X4(al[0], al[1], al[2], al[3], ad + AOFF_QL);
                #pragma unroll
                for (int p = 0; p < 6; p++) {
                    const uint32_t brow = (uint32_t)(wn * 96 + (p << 4) + b_n);
                    const uint32_t bd = sb + brow * PITCHB + b_byte + (ks << 5);
                    uint32_t bh[4], bl[4];
                    LDSM_X4(bh[0], bh[1], bh[2], bh[3], bd + AOFF_KPH);
                    LDSM_X4(bl[0], bl[1], bl[2], bl[3], bd + AOFF_KPL);
                    float* c0 = acc[p*2];
                    float* c1 = acc[p*2 + 1];
                    MMA_BF16(c0, ah, bh[0], bh[1]);
                    MMA_BF16(c0, ah, bl[0], bl[1]);
                    MMA_BF16(c0, al, bh[0], bh[1]);
                    MMA_BF16(c1, ah, bh[2], bh[3]);
                    MMA_BF16(c1, ah, bl[2], bl[3]);
                    MMA_BF16(c1, al, bh[2], bh[3]);
                }
            }
            const int row = (wm << 4) + g;
            #pragma unroll
            for (int nt = 0; nt < 12; nt++) {
                const int col = wn * 96 + nt*8 + (tg << 1);
                *(float2*)&sAll[row * SALL_P + col]       = *(float2*)&acc[nt][0];
                *(float2*)&sAll[(row + 8) * SALL_P + col] = *(float2*)&acc[nt][2];
            }
        }
        __syncthreads();

        // ---- online softmax (4 lanes per row), emit P bf16 hi/lo ----
        {
            const int r = tid >> 2, gq = tid & 3;
            const int gi = i0 + r;
            float m_old = sM[r];
            float vmax = -1e30f;
            float vals[16];
            #pragma unroll
            for (int kk = 0; kk < 16; kk++) {
                int c = gq + (kk << 2);
                float s;
                if (j0 + c <= gi) {
                    int off = c - r + 63;
                    s = (sAll[r * SALL_P + c] + sAll[r * SALL_P + 64 + off]) * scale;
                } else s = -1e30f;
                vals[kk] = s;
                vmax = fmaxf(vmax, s);
            }
            vmax = fmaxf(vmax, __shfl_xor_sync(0xffffffffu, vmax, 1));
            vmax = fmaxf(vmax, __shfl_xor_sync(0xffffffffu, vmax, 2));
            float m_new = fmaxf(m_old, vmax);
            float corr = __expf(m_old - m_new);
            float lsum = 0.f;
            #pragma unroll
            for (int kk = 0; kk < 16; kk++) {
                float p = __expf(vals[kk] - m_new);
                lsum += p;
                __nv_bfloat16 hp = __float2bfloat16_rn(p);
                __nv_bfloat16 lp = __float2bfloat16_rn(p - __bfloat162float(hp));
                int c = gq + (kk << 2);
                *(ushort*)(smem + AOFF_PH + r * PITCHB + c * 2) = __bfloat16_as_ushort(hp);
                *(ushort*)(smem + AOFF_PL + r * PITCHB + c * 2) = __bfloat16_as_ushort(lp);
            }
            lsum += __shfl_xor_sync(0xffffffffu, lsum, 1);
            lsum += __shfl_xor_sync(0xffffffffu, lsum, 2);
            if (gq == 0) {
                sM[r] = m_new;
                sL[r] = sL[r] * corr + lsum;
                sCr[r] = corr;
            }
        }
        __syncthreads();

        // ---- PV: warp = m16 x n32, O accumulated in registers ----
        {
            const float c0 = sCr[(wm << 4) + g];
            const float c1 = sCr[(wm << 4) + g + 8];
            #pragma unroll
            for (int nt = 0; nt < 4; nt++) {
                oacc[nt][0] *= c0; oacc[nt][1] *= c0;
                oacc[nt][2] *= c1; oacc[nt][3] *= c1;
            }
            #pragma unroll
            for (int ks = 0; ks < 4; ks++) {
                uint32_t ph[4], pl[4];
                const uint32_t ad = sb + a_off + (ks << 5);
                LDSM_X4(ph[0], ph[1], ph[2], ph[3], ad + AOFF_PH);
                LDSM_X4(pl[0], pl[1], pl[2], pl[3], ad + AOFF_PL);
                #pragma unroll
                for (int p = 0; p < 2; p++) {
                    const uint32_t brow = (uint32_t)((wn << 5) + (p << 4) + b_n);
                    const uint32_t bd = sb + brow * PITCHB + b_byte + (ks << 5);
                    uint32_t vh[4], vl[4];
                    LDSM_X4(vh[0], vh[1], vh[2], vh[3], bd + AOFF_VTH);
                    LDSM_X4(vl[0], vl[1], vl[2], vl[3], bd + AOFF_VTL);
                    float* o0 = oacc[p*2];
                    float* o1 = oacc[p*2 + 1];
                    MMA_BF16(o0, ph, vh[0], vh[1]);
                    MMA_BF16(o0, ph, vl[0], vl[1]);
                    MMA_BF16(o0, pl, vh[0], vh[1]);
                    MMA_BF16(o1, ph, vh[2], vh[3]);
                    MMA_BF16(o1, ph, vl[2], vl[3]);
                    MMA_BF16(o1, pl, vh[2], vh[3]);
                }
            }
        }
        __syncthreads();
    }

    // ---- normalize + write ----
    {
        const int r0 = (wm << 4) + g;
        const float linv0 = 1.0f / sL[r0];
        const float linv1 = 1.0f / sL[r0 + 8];
        #pragma unroll
        for (int nt = 0; nt < 4; nt++) {
            const int col = (wn << 5) + nt*8 + (tg << 1);
            float2 o0, o1;
            o0.x = oacc[nt][0] * linv0; o0.y = oacc[nt][1] * linv0;
            o1.x = oacc[nt][2] * linv1; o1.y = oacc[nt][3] * linv1;
            float* outp = AO + ((size_t)b * SSQ + i0 + r0) * DDIM + h * DKK + col;
            *(float2*)outp = o0;
            *(float2*)(outp + 8 * DDIM) = o1;
        }
    }
}

// ---------------- launch -------------------------------------------------
extern "C" void kernel_launch(void* const* d_in, const int* in_sizes, int n_in,
                              void* d_out, int out_size)
{
    const float* query  = (const float*)d_in[0];
    const float* key    = (const float*)d_in[1];
    const float* value  = (const float*)d_in[2];
    const float* key_pe = (const float*)d_in[3];
    const float* Wq = (const float*)d_in[4];
    const float* bq = (const float*)d_in[5];
    const float* Wk = (const float*)d_in[6];
    const float* bk = (const float*)d_in[7];
    const float* Wv = (const float*)d_in[8];
    const float* bv = (const float*)d_in[9];
    const float* Wo = (const float*)d_in[10];
    const float* bo = (const float*)d_in[11];
    (void)in_sizes; (void)n_in; (void)out_size;

    static float *gQ = nullptr, *gK = nullptr, *gV = nullptr, *gAO = nullptr;
    static bool inited = false;
    if (!inited) {
        cudaGetSymbolAddress((void**)&gQ,  g_Q);
        cudaGetSymbolAddress((void**)&gK,  g_K);
        cudaGetSymbolAddress((void**)&gV,  g_V);
        cudaGetSymbolAddress((void**)&gAO, g_AO);
        cudaFuncSetAttribute(attn_mma,
                             cudaFuncAttributeMaxDynamicSharedMemorySize, AT2_SMEM);
        cudaFuncSetAttribute(proj_qkv_tc,
                             cudaFuncAttributeMaxDynamicSharedMemorySize, PJ_SMEM);
        cudaFuncSetAttribute(proj_o_tc,
                             cudaFuncAttributeMaxDynamicSharedMemorySize, PJ_SMEM);
        inited = true;
    }

    wsplit_kernel<<<dim3(32, 32, 4), dim3(32, 8)>>>(Wq, Wk, Wv, Wo);
    proj_qkv_tc<<<dim3(8, 32, 3), 256, PJ_SMEM>>>(query, key, value, bq, bk, bv);
    attn_mma<<<dim3(SSQ / 64, BB * HH), 256, AT2_SMEM>>>(gQ, gK, gV, key_pe, gAO);
    proj_o_tc<<<dim3(8, 32, 1), 256, PJ_SMEM>>>(bo, (float*)d_out);
}

// round 8
// speedup vs baseline: 1.8803x; 1.1324x over previous
#include <cuda_runtime.h>
#include <cuda_bf16.h>
#include <cstdint>

#define BB  2
#define SSQ 2048
#define DDIM 1024
#define HH  16
#define DKK 64
#define MTOT (BB*SSQ)

// ---------------- scratch (static device, no allocations) ----------------
__device__ float g_AO[MTOT*DDIM];
__device__ __nv_bfloat16 g_Qh[MTOT*DDIM], g_Ql[MTOT*DDIM];
__device__ __nv_bfloat16 g_Kh[MTOT*DDIM], g_Kl[MTOT*DDIM];
__device__ __nv_bfloat16 g_Vh[MTOT*DDIM], g_Vl[MTOT*DDIM];
__device__ __nv_bfloat16 g_PEh[SSQ*DKK], g_PEl[SSQ*DKK];
__device__ __nv_bfloat16 g_WhT[4][DDIM*DDIM];   // W^T hi-split, [N][K] K-major
__device__ __nv_bfloat16 g_WlT[4][DDIM*DDIM];   // W^T lo-split

// ---------------- helpers ------------------------------------------------
static __device__ __forceinline__ uint32_t smem_u32(const void* p) {
    uint32_t a;
    asm("{ .reg .u64 t; cvta.to.shared.u64 t, %1; cvt.u32.u64 %0, t; }"
        : "=r"(a) : "l"(p));
    return a;
}

#define LDSM_X4(r0, r1, r2, r3, addr) \
    asm volatile("ldmatrix.sync.aligned.m8n8.x4.shared.b16 {%0,%1,%2,%3}, [%4];" \
                 : "=r"(r0), "=r"(r1), "=r"(r2), "=r"(r3) : "r"(addr))

#define LDSM_X4_T(r0, r1, r2, r3, addr) \
    asm volatile("ldmatrix.sync.aligned.m8n8.x4.trans.shared.b16 {%0,%1,%2,%3}, [%4];" \
                 : "=r"(r0), "=r"(r1), "=r"(r2), "=r"(r3) : "r"(addr))

#define MMA_BF16(c, a, b0, b1) \
    asm volatile("mma.sync.aligned.m16n8k16.row.col.f32.bf16.bf16.f32 " \
                 "{%0,%1,%2,%3}, {%4,%5,%6,%7}, {%8,%9}, {%0,%1,%2,%3};" \
                 : "+f"((c)[0]), "+f"((c)[1]), "+f"((c)[2]), "+f"((c)[3]) \
                 : "r"((a)[0]), "r"((a)[1]), "r"((a)[2]), "r"((a)[3]), \
                   "r"(b0), "r"(b1))

static __device__ __forceinline__ void split4(float4 v, uint2& h, uint2& l) {
    __nv_bfloat16 h0 = __float2bfloat16_rn(v.x);
    __nv_bfloat16 h1 = __float2bfloat16_rn(v.y);
    __nv_bfloat16 h2 = __float2bfloat16_rn(v.z);
    __nv_bfloat16 h3 = __float2bfloat16_rn(v.w);
    __nv_bfloat16 l0 = __float2bfloat16_rn(v.x - __bfloat162float(h0));
    __nv_bfloat16 l1 = __float2bfloat16_rn(v.y - __bfloat162float(h1));
    __nv_bfloat16 l2 = __float2bfloat16_rn(v.z - __bfloat162float(h2));
    __nv_bfloat16 l3 = __float2bfloat16_rn(v.w - __bfloat162float(h3));
    h.x = ((uint32_t)__bfloat16_as_ushort(h1) << 16) | __bfloat16_as_ushort(h0);
    h.y = ((uint32_t)__bfloat16_as_ushort(h3) << 16) | __bfloat16_as_ushort(h2);
    l.x = ((uint32_t)__bfloat16_as_ushort(l1) << 16) | __bfloat16_as_ushort(l0);
    l.y = ((uint32_t)__bfloat16_as_ushort(l3) << 16) | __bfloat16_as_ushort(l2);
}

static __device__ __forceinline__ uint32_t pack_hi(float x0, float x1, uint32_t& lo) {
    __nv_bfloat16 h0 = __float2bfloat16_rn(x0);
    __nv_bfloat16 h1 = __float2bfloat16_rn(x1);
    __nv_bfloat16 l0 = __float2bfloat16_rn(x0 - __bfloat162float(h0));
    __nv_bfloat16 l1 = __float2bfloat16_rn(x1 - __bfloat162float(h1));
    lo = ((uint32_t)__bfloat16_as_ushort(l1) << 16) | __bfloat16_as_ushort(l0);
    return ((uint32_t)__bfloat16_as_ushort(h1) << 16) | __bfloat16_as_ushort(h0);
}

// ---------------- W transpose + bf16 hi/lo split -------------------------
__global__ void wsplit_kernel(const float* __restrict__ W0, const float* __restrict__ W1,
                              const float* __restrict__ W2, const float* __restrict__ W3)
{
    __shared__ float t[32][33];
    const float* W = blockIdx.z == 0 ? W0 : blockIdx.z == 1 ? W1 : blockIdx.z == 2 ? W2 : W3;
    __nv_bfloat16* Wh = g_WhT[blockIdx.z];
    __nv_bfloat16* Wl = g_WlT[blockIdx.z];
    const int n0 = blockIdx.x * 32, k0 = blockIdx.y * 32;
    const int tx = threadIdx.x, ty = threadIdx.y;
    #pragma unroll
    for (int i = 0; i < 4; i++)
        t[ty + i*8][tx] = W[(size_t)(k0 + ty + i*8) * DDIM + n0 + tx];
    __syncthreads();
    #pragma unroll
    for (int i = 0; i < 4; i++) {
        float x = t[tx][ty + i*8];
        __nv_bfloat16 h = __float2bfloat16_rn(x);
        __nv_bfloat16 l = __float2bfloat16_rn(x - __bfloat162float(h));
        size_t o = (size_t)(n0 + ty + i*8) * DDIM + k0 + tx;
        Wh[o] = h; Wl[o] = l;
    }
}

__global__ void pe_split_kernel(const float* __restrict__ pe)
{
    int i = blockIdx.x * 256 + threadIdx.x;
    float x = pe[i];
    __nv_bfloat16 h = __float2bfloat16_rn(x);
    g_PEh[i] = h;
    g_PEl[i] = __float2bfloat16_rn(x - __bfloat162float(h));
}

// ---------------- mma.sync bf16x3 projection GEMM (double-buffered) ------
#define PITCHB   144
#define TILE_B   (128 * PITCHB)
#define OFF_AH   0
#define OFF_AL   TILE_B
#define OFF_WH   (2 * TILE_B)
#define OFF_WL   (3 * TILE_B)
#define PJ_BUF   (4 * TILE_B)            // 73728
#define PJ_SMEM  (2 * PJ_BUF)            // 147456

// outmode 0: fp32 C + bias;  outmode 1: bf16 hi/lo pair arrays + bias
__device__ __forceinline__ void proj_mma_body(
    const float* __restrict__ A, const __nv_bfloat16* __restrict__ WhT,
    const __nv_bfloat16* __restrict__ WlT, const float* __restrict__ bias,
    float* __restrict__ C, __nv_bfloat16* __restrict__ Ch,
    __nv_bfloat16* __restrict__ Cl, int outmode)
{
    extern __shared__ char smem[];
    const uint32_t sbase = smem_u32(smem);
    const int tid = threadIdx.x;
    const int lane = tid & 31, wid = tid >> 5;
    const int wm = wid & 1, wn = wid >> 1;
    const int bn = blockIdx.x << 7, bm = blockIdx.y << 7;

    float acc[16][4];
    #pragma unroll
    for (int i = 0; i < 16; i++)
        #pragma unroll
        for (int j = 0; j < 4; j++) acc[i][j] = 0.f;

    const int gr = tid >> 1;
    const int gc = (tid & 1) << 5;

    float4 av[8];
    uint4  whv[4], wlv[4];

    {
        const float* ap = A + (size_t)(bm + gr) * DDIM + gc;
        #pragma unroll
        for (int j = 0; j < 8; j++) av[j] = *(const float4*)(ap + j*4);
        const __nv_bfloat16* hp = WhT + (size_t)(bn + gr) * DDIM + gc;
        const __nv_bfloat16* lp = WlT + (size_t)(bn + gr) * DDIM + gc;
        #pragma unroll
        for (int j = 0; j < 4; j++) {
            whv[j] = *(const uint4*)(hp + j*8);
            wlv[j] = *(const uint4*)(lp + j*8);
        }
    }

    const uint32_t a_rel = (uint32_t)(((wm << 6) + (lane & 15)) * PITCHB)
                         + ((lane >> 4) << 4);
    const int b_n   = (lane & 7) + ((lane >> 4) << 3);
    const uint32_t b_rel = (uint32_t)(((wn << 5) + b_n) * PITCHB)
                         + ((((lane >> 3) & 1) << 3) << 1);

    for (int kt = 0; kt < 16; kt++) {
        const int p = kt & 1;
        char* buf = smem + p * PJ_BUF;
        {
            char* rowA = buf + (size_t)gr * PITCHB + gc * 2;
            #pragma unroll
            for (int j = 0; j < 8; j++) {
                uint2 uh, ul;
                split4(av[j], uh, ul);
                *(uint2*)(rowA + OFF_AH + j*8) = uh;
                *(uint2*)(rowA + OFF_AL + j*8) = ul;
            }
            #pragma unroll
            for (int j = 0; j < 4; j++) {
                *(uint4*)(rowA + OFF_WH + j*16) = whv[j];
                *(uint4*)(rowA + OFF_WL + j*16) = wlv[j];
            }
        }
        __syncthreads();

        if (kt < 15) {
            const int k0 = (kt + 1) << 6;
            const float* ap = A + (size_t)(bm + gr) * DDIM + k0 + gc;
            #pragma unroll
            for (int j = 0; j < 8; j++) av[j] = *(const float4*)(ap + j*4);
            const __nv_bfloat16* hp = WhT + (size_t)(bn + gr) * DDIM + k0 + gc;
            const __nv_bfloat16* lp = WlT + (size_t)(bn + gr) * DDIM + k0 + gc;
            #pragma unroll
            for (int j = 0; j < 4; j++) {
                whv[j] = *(const uint4*)(hp + j*8);
                wlv[j] = *(const uint4*)(lp + j*8);
            }
        }

        const uint32_t a_base = sbase + (uint32_t)(p * PJ_BUF) + a_rel;
        const uint32_t b_base = sbase + (uint32_t)(p * PJ_BUF) + b_rel;
        #pragma unroll
        for (int ks = 0; ks < 4; ks++) {
            uint32_t ah[4][4], al[4][4];
            #pragma unroll
            for (int mt = 0; mt < 4; mt++) {
                uint32_t ad = a_base + (uint32_t)(mt * 16 * PITCHB) + (ks << 5);
                LDSM_X4(ah[mt][0], ah[mt][1], ah[mt][2], ah[mt][3], ad + OFF_AH);
                LDSM_X4(al[mt][0], al[mt][1], al[mt][2], al[mt][3], ad + OFF_AL);
            }
            uint32_t bh[2][4], bl[2][4];
            #pragma unroll
            for (int pr = 0; pr < 2; pr++) {
                uint32_t bd = b_base + (uint32_t)(pr * 16 * PITCHB) + (ks << 5);
                LDSM_X4(bh[pr][0], bh[pr][1], bh[pr][2], bh[pr][3], bd + OFF_WH);
                LDSM_X4(bl[pr][0], bl[pr][1], bl[pr][2], bl[pr][3], bd + OFF_WL);
            }
            #pragma unroll
            for (int mt = 0; mt < 4; mt++)
                #pragma unroll
                for (int nt = 0; nt < 4; nt++) {
                    const int pr = nt >> 1, f = (nt & 1) << 1;
                    float* c = acc[mt*4 + nt];
                    MMA_BF16(c, ah[mt], bh[pr][f], bh[pr][f+1]);
                    MMA_BF16(c, ah[mt], bl[pr][f], bl[pr][f+1]);
                    MMA_BF16(c, al[mt], bh[pr][f], bh[pr][f+1]);
                }
        }
        // no trailing sync: next store targets the other buffer; the next
        // barrier proves all warps finished this MMA before buf reuse.
    }

    const int g = lane >> 2, tg = lane & 3;
    #pragma unroll
    for (int mt = 0; mt < 4; mt++) {
        const int row0 = bm + (wm << 6) + mt*16 + g;
        #pragma unroll
        for (int nt = 0; nt < 4; nt++) {
            const int col = bn + (wn << 5) + nt*8 + (tg << 1);
            const float* c = acc[mt*4 + nt];
            float b0 = bias[col], b1 = bias[col + 1];
            if (outmode == 0) {
                float2 o0, o1;
                o0.x = c[0] + b0; o0.y = c[1] + b1;
                o1.x = c[2] + b0; o1.y = c[3] + b1;
                *(float2*)(C + (size_t)row0 * DDIM + col)       = o0;
                *(float2*)(C + (size_t)(row0 + 8) * DDIM + col) = o1;
            } else {
                uint32_t lo0, lo1;
                uint32_t hi0 = pack_hi(c[0] + b0, c[1] + b1, lo0);
                uint32_t hi1 = pack_hi(c[2] + b0, c[3] + b1, lo1);
                *(uint32_t*)(Ch + (size_t)row0 * DDIM + col)       = hi0;
                *(uint32_t*)(Cl + (size_t)row0 * DDIM + col)       = lo0;
                *(uint32_t*)(Ch + (size_t)(row0 + 8) * DDIM + col) = hi1;
                *(uint32_t*)(Cl + (size_t)(row0 + 8) * DDIM + col) = lo1;
            }
        }
    }
}

__global__ __launch_bounds__(256, 1)
void proj_qkv_tc(const float* __restrict__ q, const float* __restrict__ k,
                 const float* __restrict__ v, const float* __restrict__ bq,
                 const float* __restrict__ bk, const float* __restrict__ bv)
{
    const int z = blockIdx.z;
    const float* A    = z == 0 ? q  : z == 1 ? k  : v;
    const float* bias = z == 0 ? bq : z == 1 ? bk : bv;
    __nv_bfloat16* Ch = z == 0 ? g_Qh : z == 1 ? g_Kh : g_Vh;
    __nv_bfloat16* Cl = z == 0 ? g_Ql : z == 1 ? g_Kl : g_Vl;
    proj_mma_body(A, g_WhT[z], g_WlT[z], bias, nullptr, Ch, Cl, 1);
}

__global__ __launch_bounds__(256, 1)
void proj_o_tc(const float* __restrict__ bo, float* __restrict__ out)
{
    proj_mma_body(g_AO, g_WhT[3], g_WlT[3], bo, out, nullptr, nullptr, 0);
}

// ---------------- mma.sync flash attention (bf16 pre-split inputs) -------
// smem byte offsets, all bf16 tiles pitch 144B:
#define AOFF_QH   0            // 64 rows
#define AOFF_QL   9216
#define AOFF_KPH  18432        // 192 rows: K 0..63, PE 64..191
#define AOFF_KPL  46080
#define AOFF_V0H  73728        // V double buffer, 64 rows each
#define AOFF_V0L  82944
#define AOFF_V1H  92160
#define AOFF_V1L  101376
#define AOFF_PH   110592       // 64 rows
#define AOFF_PL   119808
#define AOFF_ALL  129024       // fp32 64 x 196
#define AOFF_M    179200
#define AOFF_L    179456
#define AOFF_CR   179712
#define AT3_SMEM  179968
#define SALL_P    196

__global__ __launch_bounds__(256, 1)
void attn_mma(const float* __restrict__ unused, float* __restrict__ AO)
{
    extern __shared__ char smem[];
    const uint32_t sb = smem_u32(smem);
    float* sAll = (float*)(smem + AOFF_ALL);
    float* sM   = (float*)(smem + AOFF_M);
    float* sL   = (float*)(smem + AOFF_L);
    float* sCr  = (float*)(smem + AOFF_CR);

    const int tid = threadIdx.x;
    const int lane = tid & 31, wid = tid >> 5;
    const int wm = wid & 3, wn = wid >> 2;       // 4m x 2n
    const int i0 = (gridDim.x - 1 - blockIdx.x) << 6;   // heavy tiles first
    const int bh = blockIdx.y;
    const int b = bh >> 4, h = bh & 15;
    const float scale = 0.125f;

    const size_t rowbase = (size_t)b * SSQ * DDIM + h * DKK;

    // copy-lane mappings (bf16 tiles, 64 rows x 128B)
    const int qr = tid >> 2;                  // 0..63
    const int qcB = (tid & 3) << 5;           // byte 0,32,64,96
    const int pr = tid >> 1;                  // 0..127
    const int pcB = (tid & 1) << 6;           // byte 0,64

    // ---- Q tile (once) ----
    {
        const __nv_bfloat16* qh = g_Qh + rowbase + (size_t)(i0 + qr) * DDIM + (qcB >> 1);
        const __nv_bfloat16* ql = g_Ql + rowbase + (size_t)(i0 + qr) * DDIM + (qcB >> 1);
        char* dst = smem + qr * PITCHB + qcB;
        *(uint4*)(dst + AOFF_QH)      = *(const uint4*)(qh);
        *(uint4*)(dst + AOFF_QH + 16) = *(const uint4*)(qh + 8);
        *(uint4*)(dst + AOFF_QL)      = *(const uint4*)(ql);
        *(uint4*)(dst + AOFF_QL + 16) = *(const uint4*)(ql + 8);
    }
    if (tid < 64) { sM[tid] = -1e30f; sL[tid] = 0.f; }

    float oacc[4][4];
    #pragma unroll
    for (int i = 0; i < 4; i++)
        #pragma unroll
        for (int j = 0; j < 4; j++) oacc[i][j] = 0.f;

    // ldmatrix lane bases
    const uint32_t a_off = (uint32_t)(((wm << 4) + (lane & 15)) * PITCHB)
                         + ((lane >> 4) << 4);
    const int b_n = (lane & 7) + ((lane >> 4) << 3);
    const uint32_t b_byte = ((lane >> 3) & 1) << 4;
    // V trans-ldmatrix: row = lane&15 (s), byte = (lane>>4)<<4 (d half)
    const uint32_t v_off = (uint32_t)((lane & 15) * PITCHB) + ((lane >> 4) << 4);

    const int g = lane >> 2, tg = lane & 3;
    const int ntiles = (i0 >> 6) + 1;

    // ---- initial loads: K(0), PE(0), V(0) -> buf0 ----
    {
        const int j0 = 0;
        const int base0 = SSQ - 64 - i0 + j0;
        const __nv_bfloat16* kh = g_Kh + rowbase + (size_t)(j0 + qr) * DDIM + (qcB >> 1);
        const __nv_bfloat16* kl = g_Kl + rowbase + (size_t)(j0 + qr) * DDIM + (qcB >> 1);
        char* dk = smem + qr * PITCHB + qcB;
        *(uint4*)(dk + AOFF_KPH)      = *(const uint4*)(kh);
        *(uint4*)(dk + AOFF_KPH + 16) = *(const uint4*)(kh + 8);
        *(uint4*)(dk + AOFF_KPL)      = *(const uint4*)(kl);
        *(uint4*)(dk + AOFF_KPL + 16) = *(const uint4*)(kl + 8);
        const __nv_bfloat16* vh = g_Vh + rowbase + (size_t)(j0 + qr) * DDIM + (qcB >> 1);
        const __nv_bfloat16* vl = g_Vl + rowbase + (size_t)(j0 + qr) * DDIM + (qcB >> 1);
        *(uint4*)(dk + AOFF_V0H)      = *(const uint4*)(vh);
        *(uint4*)(dk + AOFF_V0H + 16) = *(const uint4*)(vh + 8);
        *(uint4*)(dk + AOFF_V0L)      = *(const uint4*)(vl);
        *(uint4*)(dk + AOFF_V0L + 16) = *(const uint4*)(vl + 8);
        int l = base0 + pr;
        l = l < 0 ? 0 : (l > SSQ - 1 ? SSQ - 1 : l);
        const __nv_bfloat16* ph = g_PEh + l * DKK + (pcB >> 1);
        const __nv_bfloat16* pl = g_PEl + l * DKK + (pcB >> 1);
        char* dp = smem + (64 + pr) * PITCHB + pcB;
        #pragma unroll
        for (int j = 0; j < 4; j++) {
            *(uint4*)(dp + AOFF_KPH + j*16) = *(const uint4*)(ph + j*8);
            *(uint4*)(dp + AOFF_KPL + j*16) = *(const uint4*)(pl + j*8);
        }
    }
    __syncthreads();

    for (int kt = 0; kt < ntiles; kt++) {
        const int j0 = kt << 6;
        const uint32_t vbufH = (kt & 1) ? AOFF_V1H : AOFF_V0H;
        const uint32_t vbufL = (kt & 1) ? AOFF_V1L : AOFF_V0L;

        // ---- score GEMM: warp = m16 x n96 over [K|PE] ----
        {
            float acc[12][4];
            #pragma unroll
            for (int i = 0; i < 12; i++)
                #pragma unroll
                for (int j = 0; j < 4; j++) acc[i][j] = 0.f;

            #pragma unroll
            for (int ks = 0; ks < 4; ks++) {
                uint32_t ah[4], al[4];
                const uint32_t ad = sb + a_off + (ks << 5);
                LDSM_X4(ah[0], ah[1], ah[2], ah[3], ad + AOFF_QH);
                LDSM_X4(al[0], al[1], al[2], al[3], ad + AOFF_QL);
                #pragma unroll
                for (int p = 0; p < 6; p++) {
                    const uint32_t brow = (uint32_t)(wn * 96 + (p << 4) + b_n);
                    const uint32_t bd = sb + brow * PITCHB + b_byte + (ks << 5);
                    uint32_t bhv[4], blv[4];
                    LDSM_X4(bhv[0], bhv[1], bhv[2], bhv[3], bd + AOFF_KPH);
                    LDSM_X4(blv[0], blv[1], blv[2], blv[3], bd + AOFF_KPL);
                    float* c0 = acc[p*2];
                    float* c1 = acc[p*2 + 1];
                    MMA_BF16(c0, ah, bhv[0], bhv[1]);
                    MMA_BF16(c0, ah, blv[0], blv[1]);
                    MMA_BF16(c0, al, bhv[0], bhv[1]);
                    MMA_BF16(c1, ah, bhv[2], bhv[3]);
                    MMA_BF16(c1, ah, blv[2], blv[3]);
                    MMA_BF16(c1, al, bhv[2], bhv[3]);
                }
            }
            const int row = (wm << 4) + g;
            #pragma unroll
            for (int nt = 0; nt < 12; nt++) {
                const int col = wn * 96 + nt*8 + (tg << 1);
                *(float2*)&sAll[row * SALL_P + col]       = *(float2*)&acc[nt][0];
                *(float2*)&sAll[(row + 8) * SALL_P + col] = *(float2*)&acc[nt][2];
            }
        }
        __syncthreads();

        // ---- online softmax, emit P bf16 hi/lo ----
        {
            const int r = tid >> 2, gq = tid & 3;
            const int gi = i0 + r;
            float m_old = sM[r];
            float vmax = -1e30f;
            float vals[16];
            #pragma unroll
            for (int kk = 0; kk < 16; kk++) {
                int c = gq + (kk << 2);
                float s;
                if (j0 + c <= gi) {
                    int off = c - r + 63;
                    s = (sAll[r * SALL_P + c] + sAll[r * SALL_P + 64 + off]) * scale;
                } else s = -1e30f;
                vals[kk] = s;
                vmax = fmaxf(vmax, s);
            }
            vmax = fmaxf(vmax, __shfl_xor_sync(0xffffffffu, vmax, 1));
            vmax = fmaxf(vmax, __shfl_xor_sync(0xffffffffu, vmax, 2));
            float m_new = fmaxf(m_old, vmax);
            float corr = __expf(m_old - m_new);
            float lsum = 0.f;
            #pragma unroll
            for (int kk = 0; kk < 16; kk++) {
                float p = __expf(vals[kk] - m_new);
                lsum += p;
                __nv_bfloat16 hp = __float2bfloat16_rn(p);
                __nv_bfloat16 lp = __float2bfloat16_rn(p - __bfloat162float(hp));
                int c = gq + (kk << 2);
                *(ushort*)(smem + AOFF_PH + r * PITCHB + c * 2) = __bfloat16_as_ushort(hp);
                *(ushort*)(smem + AOFF_PL + r * PITCHB + c * 2) = __bfloat16_as_ushort(lp);
            }
            lsum += __shfl_xor_sync(0xffffffffu, lsum, 1);
            lsum += __shfl_xor_sync(0xffffffffu, lsum, 2);
            if (gq == 0) {
                sM[r] = m_new;
                sL[r] = sL[r] * corr + lsum;
                sCr[r] = corr;
            }
        }
        __syncthreads();

        // ---- PV (reads P, V[buf]) + next-tile loads (K, PE, V[other buf]) ----
        if (kt + 1 < ntiles) {
            const int j1 = (kt + 1) << 6;
            const int base1 = SSQ - 64 - i0 + j1;
            const uint32_t nvH = (kt & 1) ? AOFF_V0H : AOFF_V1H;
            const uint32_t nvL = (kt & 1) ? AOFF_V0L : AOFF_V1L;
            const __nv_bfloat16* kh = g_Kh + rowbase + (size_t)(j1 + qr) * DDIM + (qcB >> 1);
            const __nv_bfloat16* kl = g_Kl + rowbase + (size_t)(j1 + qr) * DDIM + (qcB >> 1);
            char* dk = smem + qr * PITCHB + qcB;
            *(uint4*)(dk + AOFF_KPH)      = *(const uint4*)(kh);
            *(uint4*)(dk + AOFF_KPH + 16) = *(const uint4*)(kh + 8);
            *(uint4*)(dk + AOFF_KPL)      = *(const uint4*)(kl);
            *(uint4*)(dk + AOFF_KPL + 16) = *(const uint4*)(kl + 8);
            const __nv_bfloat16* vh = g_Vh + rowbase + (size_t)(j1 + qr) * DDIM + (qcB >> 1);
            const __nv_bfloat16* vl = g_Vl + rowbase + (size_t)(j1 + qr) * DDIM + (qcB >> 1);
            *(uint4*)(dk + nvH)      = *(const uint4*)(vh);
            *(uint4*)(dk + nvH + 16) = *(const uint4*)(vh + 8);
            *(uint4*)(dk + nvL)      = *(const uint4*)(vl);
            *(uint4*)(dk + nvL + 16) = *(const uint4*)(vl + 8);
            int l = base1 + pr;
            l = l < 0 ? 0 : (l > SSQ - 1 ? SSQ - 1 : l);
            const __nv_bfloat16* ph = g_PEh + l * DKK + (pcB >> 1);
            const __nv_bfloat16* pl = g_PEl + l * DKK + (pcB >> 1);
            char* dp = smem + (64 + pr) * PITCHB + pcB;
            #pragma unroll
            for (int j = 0; j < 4; j++) {
                *(uint4*)(dp + AOFF_KPH + j*16) = *(const uint4*)(ph + j*8);
                *(uint4*)(dp + AOFF_KPL + j*16) = *(const uint4*)(pl + j*8);
            }
        }
        {
            const float c0 = sCr[(wm << 4) + g];
            const float c1 = sCr[(wm << 4) + g + 8];
            #pragma unroll
            for (int nt = 0; nt < 4; nt++) {
                oacc[nt][0] *= c0; oacc[nt][1] *= c0;
                oacc[nt][2] *= c1; oacc[nt][3] *= c1;
            }
            #pragma unroll
            for (int ks = 0; ks < 4; ks++) {
                uint32_t ph[4], pl[4];
                const uint32_t ad = sb + a_off + (ks << 5);
                LDSM_X4(ph[0], ph[1], ph[2], ph[3], ad + AOFF_PH);
                LDSM_X4(pl[0], pl[1], pl[2], pl[3], ad + AOFF_PL);
                #pragma unroll
                for (int p = 0; p < 2; p++) {
                    // V via trans-ldmatrix: rows s = ks*16+(lane&15), d-block = wn*32+p*16
                    const uint32_t vd = sb + v_off + (uint32_t)((ks << 4) * PITCHB)
                                      + (uint32_t)((wn << 6) + (p << 5));
                    uint32_t vh[4], vl[4];
                    LDSM_X4_T(vh[0], vh[1], vh[2], vh[3], vd + vbufH);
                    LDSM_X4_T(vl[0], vl[1], vl[2], vl[3], vd + vbufL);
                    float* o0 = oacc[p*2];
                    float* o1 = oacc[p*2 + 1];
                    MMA_BF16(o0, ph, vh[0], vh[1]);
                    MMA_BF16(o0, ph, vl[0], vl[1]);
                    MMA_BF16(o0, pl, vh[0], vh[1]);
                    MMA_BF16(o1, ph, vh[2], vh[3]);
                    MMA_BF16(o1, ph, vl[2], vl[3]);
                    MMA_BF16(o1, pl, vh[2], vh[3]);
                }
            }
        }
        __syncthreads();
    }

    // ---- normalize + write ----
    {
        const int r0 = (wm << 4) + g;
        const float linv0 = 1.0f / sL[r0];
        const float linv1 = 1.0f / sL[r0 + 8];
        #pragma unroll
        for (int nt = 0; nt < 4; nt++) {
            const int col = (wn << 5) + nt*8 + (tg << 1);
            float2 o0, o1;
            o0.x = oacc[nt][0] * linv0; o0.y = oacc[nt][1] * linv0;
            o1.x = oacc[nt][2] * linv1; o1.y = oacc[nt][3] * linv1;
            float* outp = AO + ((size_t)b * SSQ + i0 + r0) * DDIM + h * DKK + col;
            *(float2*)outp = o0;
            *(float2*)(outp + 8 * DDIM) = o1;
        }
    }
}

// ---------------- launch -------------------------------------------------
extern "C" void kernel_launch(void* const* d_in, const int* in_sizes, int n_in,
                              void* d_out, int out_size)
{
    const float* query  = (const float*)d_in[0];
    const float* key    = (const float*)d_in[1];
    const float* value  = (const float*)d_in[2];
    const float* key_pe = (const float*)d_in[3];
    const float* Wq = (const float*)d_in[4];
    const float* bq = (const float*)d_in[5];
    const float* Wk = (const float*)d_in[6];
    const float* bk = (const float*)d_in[7];
    const float* Wv = (const float*)d_in[8];
    const float* bv = (const float*)d_in[9];
    const float* Wo = (const float*)d_in[10];
    const float* bo = (const float*)d_in[11];
    (void)in_sizes; (void)n_in; (void)out_size;

    static float* gAO = nullptr;
    static bool inited = false;
    if (!inited) {
        cudaGetSymbolAddress((void**)&gAO, g_AO);
        cudaFuncSetAttribute(attn_mma,
                             cudaFuncAttributeMaxDynamicSharedMemorySize, AT3_SMEM);
        cudaFuncSetAttribute(proj_qkv_tc,
                             cudaFuncAttributeMaxDynamicSharedMemorySize, PJ_SMEM);
        cudaFuncSetAttribute(proj_o_tc,
                             cudaFuncAttributeMaxDynamicSharedMemorySize, PJ_SMEM);
        inited = true;
    }

    wsplit_kernel<<<dim3(32, 32, 4), dim3(32, 8)>>>(Wq, Wk, Wv, Wo);
    pe_split_kernel<<<SSQ * DKK / 256, 256>>>(key_pe);
    proj_qkv_tc<<<dim3(8, 32, 3), 256, PJ_SMEM>>>(query, key, value, bq, bk, bv);
    attn_mma<<<dim3(SSQ / 64, BB * HH), 256, AT3_SMEM>>>(nullptr, gAO);
    proj_o_tc<<<dim3(8, 32, 1), 256, PJ_SMEM>>>(bo, (float*)d_out);
}